// round 16
// baseline (speedup 1.0000x reference)
#include <cuda_runtime.h>

// CorrespondenceSoftNMS, N=8192, DELTA=0.1, SIGMA=0.05, JOINT_NMS=true
//
// Two fused kernels (last-arriving-block pattern, fence+atomic, no spins):
//   K1 rank_scatter: partial ranks (strict score compare) per j-chunk;
//      the 16th finishing chunk-block per row-block scatters rows into
//      sorted order (ties via atomic sub-slot; output-invariant because
//      suppression uses strict compares) and precomputes a_i.
//   K2 nms_fin: triangular penalty tiles (4 per block); the 16th finishing
//      group-block per row-block reduces the 16 partials per row, applies
//      the final decay, scatters to out, and resets tie counters.
//
// arg2 = a_i + a_j + (2L p_i).p_j in log2 domain; skip when arg2 < -30
// (penalty err <= 8192*2^-30 -> ~2e-4 relative on out, threshold 1e-3).
// Hot loop: fma.rn.f32x2 packed math on SoA smem tiles.

#define NMAX    8192
#define TILE    128
#define NBLK    (NMAX/TILE)  // 64 row blocks
#define RCH     16           // j-chunks for rank
#define G       4            // j-tiles per nms block
#define NGROUP  16           // 64 tiles / G

typedef unsigned long long ull;

__device__ float4 g_SA[NMAX];                        // sorted (sx, sy, sz, tx)
__device__ float4 g_SB[NMAX];                        // sorted (ty, tz, a, score)
__device__ int    g_sidx[NMAX];                      // sorted pos -> original idx
__device__ __align__(16) int   g_rankt[NMAX][RCH];   // partial ranks (row-major)
__device__ int    g_tiecnt[NMAX];                    // tie sub-slot counters
__device__ __align__(16) float g_partial[NMAX][NGROUP];
__device__ int    g_cnt1[NBLK];                      // K1 arrival counters
__device__ int    g_cnt2[NBLK];                      // K2 arrival counters

__device__ __forceinline__ float ex2f(float x) {
    float r;
    asm("ex2.approx.f32 %0, %1;" : "=f"(r) : "f"(x));
    return r;
}
__device__ __forceinline__ ull pack2(float lo, float hi) {
    ull r;
    asm("mov.b64 %0, {%1, %2};" : "=l"(r) : "f"(lo), "f"(hi));
    return r;
}
__device__ __forceinline__ ull add2(ull a, ull b) {
    ull r;
    asm("add.rn.f32x2 %0, %1, %2;" : "=l"(r) : "l"(a), "l"(b));
    return r;
}
__device__ __forceinline__ ull ffma2(ull a, ull b, ull c) {
    ull r;
    asm("fma.rn.f32x2 %0, %1, %2, %3;" : "=l"(r) : "l"(a), "l"(b), "l"(c));
    return r;
}
__device__ __forceinline__ float lo32(ull v) {
    return __int_as_float((int)(unsigned int)v);
}
__device__ __forceinline__ float hi32(ull v) {
    return __int_as_float((int)(unsigned int)(v >> 32));
}

// ---------------- K1: rank + (last block) scatter ----------------
__global__ __launch_bounds__(TILE) void rank_scatter_kernel(
    const float* __restrict__ src, const float* __restrict__ tgt,
    const float* __restrict__ sc, int n) {
    const int bx = blockIdx.x, by = blockIdx.y;
    const int i = bx * TILE + threadIdx.x;
    const float si = sc[i];
    const int jchunk = n / RCH;                      // 512
    const float4* s4 = (const float4*)(sc + by * jchunk);

    int cnt = 0;
    #pragma unroll 8
    for (int q = 0; q < jchunk / 4; ++q) {
        float4 S = __ldg(&s4[q]);                    // uniform broadcast
        cnt += (S.x > si);
        cnt += (S.y > si);
        cnt += (S.z > si);
        cnt += (S.w > si);
    }
    g_rankt[i][by] = cnt;

    __threadfence();
    __shared__ int s_last;
    if (threadIdx.x == 0)
        s_last = (atomicAdd(&g_cnt1[bx], 1) == RCH - 1);
    __syncthreads();
    if (!s_last) return;

    // Last-arriving chunk block for this row block: all 16 partials visible.
    const int4* rp = (const int4*)g_rankt[i];        // 64B contiguous
    int4 r0 = rp[0], r1 = rp[1], r2 = rp[2], r3 = rp[3];
    int r = ((r0.x + r0.y) + (r0.z + r0.w)) + ((r1.x + r1.y) + (r1.z + r1.w))
          + ((r2.x + r2.y) + (r2.z + r2.w)) + ((r3.x + r3.y) + (r3.z + r3.w));
    // Tie classes occupy consecutive ranks; sub-slot keeps it a bijection.
    int pos = r + atomicAdd(&g_tiecnt[r], 1);        // tiecnt reset in K2

    float sx = src[3*i+0], sy = src[3*i+1], sz = src[3*i+2];
    float tx = tgt[3*i+0], ty = tgt[3*i+1], tz = tgt[3*i+2];
    const float L = 144.26950408889634f;             // log2(e)/DELTA^2
    float a = -L * (sx*sx + sy*sy + sz*sz + tx*tx + ty*ty + tz*tz);

    g_SA[pos]   = make_float4(sx, sy, sz, tx);
    g_SB[pos]   = make_float4(ty, tz, a, si);
    g_sidx[pos] = i;

    if (threadIdx.x == 0) g_cnt1[bx] = 0;            // ready for next replay
}

// ---------------- K2: triangular penalty + (last block) finalize ----------------
__global__ __launch_bounds__(TILE) void nms_fin_kernel(float* __restrict__ out,
                                                       int n) {
    const int bi = blockIdx.x;                       // row block
    const int g  = blockIdx.y;                       // tile group
    const int i  = bi * TILE + threadIdx.x;

    __shared__ __align__(16) float s_x[TILE], s_y[TILE], s_z[TILE];
    __shared__ __align__(16) float s_u[TILE], s_v[TILE], s_w[TILE];
    __shared__ __align__(16) float s_a[TILE], s_s[TILE];

    if (g * G > bi) {                                // no suppressor tiles here
        g_partial[i][g] = 0.0f;
    } else {
        const float4 Ai = g_SA[i];
        const float4 Bi = g_SB[i];
        const float twoL = 288.5390081777927f;       // 2*log2(e)/DELTA^2
        const ull w0 = pack2(twoL*Ai.x, twoL*Ai.x);
        const ull w1 = pack2(twoL*Ai.y, twoL*Ai.y);
        const ull w2 = pack2(twoL*Ai.z, twoL*Ai.z);
        const ull w3 = pack2(twoL*Ai.w, twoL*Ai.w);
        const ull w4 = pack2(twoL*Bi.x, twoL*Bi.x);
        const ull w5 = pack2(twoL*Bi.y, twoL*Bi.y);
        const ull ai2 = pack2(Bi.z, Bi.z);
        const float si = Bi.w;
        const float T = -30.0f;

        float pen = 0.0f;
        const int t1 = min(bi, g * G + (G - 1));

        for (int tj = g * G; tj <= t1; ++tj) {
            int j = tj * TILE + threadIdx.x;
            float4 A = g_SA[j];
            float4 B = g_SB[j];
            s_x[threadIdx.x] = A.x;
            s_y[threadIdx.x] = A.y;
            s_z[threadIdx.x] = A.z;
            s_u[threadIdx.x] = A.w;
            s_v[threadIdx.x] = B.x;
            s_w[threadIdx.x] = B.y;
            s_a[threadIdx.x] = B.z;
            s_s[threadIdx.x] = B.w;
            __syncthreads();

            const ulonglong2* px = (const ulonglong2*)s_x;
            const ulonglong2* py = (const ulonglong2*)s_y;
            const ulonglong2* pz = (const ulonglong2*)s_z;
            const ulonglong2* pu = (const ulonglong2*)s_u;
            const ulonglong2* pv = (const ulonglong2*)s_v;
            const ulonglong2* pw = (const ulonglong2*)s_w;
            const ulonglong2* pa = (const ulonglong2*)s_a;

            #pragma unroll 4
            for (int q = 0; q < TILE / 4; ++q) {
                ulonglong2 X = px[q];                // broadcast LDS.128
                ulonglong2 Y = py[q];
                ulonglong2 Z = pz[q];
                ulonglong2 U = pu[q];
                ulonglong2 V = pv[q];
                ulonglong2 W = pw[q];
                ulonglong2 AA = pa[q];

                ull acc0 = add2(ai2, AA.x);          // j = 4q, 4q+1
                ull acc1 = add2(ai2, AA.y);          // j = 4q+2, 4q+3
                acc0 = ffma2(w0, X.x, acc0);  acc1 = ffma2(w0, X.y, acc1);
                acc0 = ffma2(w1, Y.x, acc0);  acc1 = ffma2(w1, Y.y, acc1);
                acc0 = ffma2(w2, Z.x, acc0);  acc1 = ffma2(w2, Z.y, acc1);
                acc0 = ffma2(w3, U.x, acc0);  acc1 = ffma2(w3, U.y, acc1);
                acc0 = ffma2(w4, V.x, acc0);  acc1 = ffma2(w4, V.y, acc1);
                acc0 = ffma2(w5, W.x, acc0);  acc1 = ffma2(w5, W.y, acc1);

                float a0 = lo32(acc0), a1 = hi32(acc0);
                float a2 = lo32(acc1), a3 = hi32(acc1);

                // Rare path: strict score check handles ties and the
                // diagonal j==i (arg2 ~ 0, s_i > s_i false).
                if ((a0 > T) | (a1 > T) | (a2 > T) | (a3 > T)) {
                    int jb = q * 4;
                    if (a0 > T && s_s[jb+0] > si) pen += ex2f(a0);
                    if (a1 > T && s_s[jb+1] > si) pen += ex2f(a1);
                    if (a2 > T && s_s[jb+2] > si) pen += ex2f(a2);
                    if (a3 > T && s_s[jb+3] > si) pen += ex2f(a3);
                }
            }
            __syncthreads();
        }
        g_partial[i][g] = pen;
    }

    __threadfence();
    __shared__ int s_last;
    if (threadIdx.x == 0)
        s_last = (atomicAdd(&g_cnt2[bi], 1) == NGROUP - 1);
    __syncthreads();
    if (!s_last) return;

    // Last-arriving group block for this row block: finalize its 128 rows.
    const float4* pp = (const float4*)g_partial[i];  // 64B contiguous
    float4 a = pp[0], b = pp[1], c = pp[2], d = pp[3];
    float P = ((a.x + a.y) + (a.z + a.w)) + ((b.x + b.y) + (b.z + b.w))
            + ((c.x + c.y) + (c.z + c.w)) + ((d.x + d.y) + (d.z + d.w));
    const float C = 28.853900817779268f;             // log2(e)/SIGMA
    out[g_sidx[i]] = g_SB[i].w * ex2f(-P * C);

    g_tiecnt[i] = 0;                                 // reset for next replay
    if (threadIdx.x == 0) g_cnt2[bi] = 0;
}

extern "C" void kernel_launch(void* const* d_in, const int* in_sizes, int n_in,
                              void* d_out, int out_size) {
    const float* src = (const float*)d_in[0];
    const float* tgt = (const float*)d_in[1];
    const float* sc  = (const float*)d_in[2];
    float* out = (float*)d_out;
    const int n = in_sizes[2];                       // 8192

    dim3 g1(NBLK, RCH);
    rank_scatter_kernel<<<g1, TILE>>>(src, tgt, sc, n);
    dim3 g2(NBLK, NGROUP);
    nms_fin_kernel<<<g2, TILE>>>(out, n);
}

// round 17
// speedup vs baseline: 1.0406x; 1.0406x over previous
#include <cuda_runtime.h>

// CorrespondenceSoftNMS, N=8192, DELTA=0.1, SIGMA=0.05, JOINT_NMS=true
//
// Two fused kernels (last-arriving-block pattern, fence+atomic, no spins):
//   K1 rank_scatter: partial ranks (strict score compare) per j-chunk;
//      the 16th finishing chunk-block per row-block scatters rows into
//      sorted order (ties via atomic sub-slot; output-invariant because
//      suppression uses strict compares) and precomputes a_i.
//   K2 nms_fin: triangular penalty tiles (4 per block); the 16th finishing
//      group-block per row-block reduces the 16 partials per row, applies
//      the final decay, scatters to out, and resets tie counters.
//
// arg2 = a_i + a_j + (2L p_i).p_j in log2 domain; skip when arg2 < -30
// (penalty err <= 8192*2^-30 -> ~2e-4 relative on out, threshold 1e-3).
// Hot loop: fma.rn.f32x2 packed math on SoA smem tiles.

#define NMAX    8192
#define TILE    128
#define NBLK    (NMAX/TILE)  // 64 row blocks
#define RCH     16           // j-chunks for rank
#define G       4            // j-tiles per nms block
#define NGROUP  16           // 64 tiles / G

typedef unsigned long long ull;

__device__ float4 g_SA[NMAX];                        // sorted (sx, sy, sz, tx)
__device__ float4 g_SB[NMAX];                        // sorted (ty, tz, a, score)
__device__ int    g_sidx[NMAX];                      // sorted pos -> original idx
__device__ __align__(16) int   g_rankt[NMAX][RCH];   // partial ranks (row-major)
__device__ int    g_tiecnt[NMAX];                    // tie sub-slot counters
__device__ __align__(16) float g_partial[NMAX][NGROUP];
__device__ int    g_cnt1[NBLK];                      // K1 arrival counters
__device__ int    g_cnt2[NBLK];                      // K2 arrival counters

__device__ __forceinline__ float ex2f(float x) {
    float r;
    asm("ex2.approx.f32 %0, %1;" : "=f"(r) : "f"(x));
    return r;
}
__device__ __forceinline__ ull pack2(float lo, float hi) {
    ull r;
    asm("mov.b64 %0, {%1, %2};" : "=l"(r) : "f"(lo), "f"(hi));
    return r;
}
__device__ __forceinline__ ull add2(ull a, ull b) {
    ull r;
    asm("add.rn.f32x2 %0, %1, %2;" : "=l"(r) : "l"(a), "l"(b));
    return r;
}
__device__ __forceinline__ ull ffma2(ull a, ull b, ull c) {
    ull r;
    asm("fma.rn.f32x2 %0, %1, %2, %3;" : "=l"(r) : "l"(a), "l"(b), "l"(c));
    return r;
}
__device__ __forceinline__ float lo32(ull v) {
    return __int_as_float((int)(unsigned int)v);
}
__device__ __forceinline__ float hi32(ull v) {
    return __int_as_float((int)(unsigned int)(v >> 32));
}

// ---------------- K1: rank + (last block) scatter ----------------
__global__ __launch_bounds__(TILE) void rank_scatter_kernel(
    const float* __restrict__ src, const float* __restrict__ tgt,
    const float* __restrict__ sc, int n) {
    const int bx = blockIdx.x, by = blockIdx.y;
    const int i = bx * TILE + threadIdx.x;
    const float si = sc[i];
    const int jchunk = n / RCH;                      // 512
    const float4* s4 = (const float4*)(sc + by * jchunk);

    int cnt = 0;
    #pragma unroll 8
    for (int q = 0; q < jchunk / 4; ++q) {
        float4 S = __ldg(&s4[q]);                    // uniform broadcast
        cnt += (S.x > si);
        cnt += (S.y > si);
        cnt += (S.z > si);
        cnt += (S.w > si);
    }
    g_rankt[i][by] = cnt;

    __threadfence();
    __shared__ int s_last;
    if (threadIdx.x == 0)
        s_last = (atomicAdd(&g_cnt1[bx], 1) == RCH - 1);
    __syncthreads();
    if (!s_last) return;

    // Last-arriving chunk block for this row block: all 16 partials visible.
    const int4* rp = (const int4*)g_rankt[i];        // 64B contiguous
    int4 r0 = rp[0], r1 = rp[1], r2 = rp[2], r3 = rp[3];
    int r = ((r0.x + r0.y) + (r0.z + r0.w)) + ((r1.x + r1.y) + (r1.z + r1.w))
          + ((r2.x + r2.y) + (r2.z + r2.w)) + ((r3.x + r3.y) + (r3.z + r3.w));
    // Tie classes occupy consecutive ranks; sub-slot keeps it a bijection.
    int pos = r + atomicAdd(&g_tiecnt[r], 1);        // tiecnt reset in K2

    float sx = src[3*i+0], sy = src[3*i+1], sz = src[3*i+2];
    float tx = tgt[3*i+0], ty = tgt[3*i+1], tz = tgt[3*i+2];
    const float L = 144.26950408889634f;             // log2(e)/DELTA^2
    float a = -L * (sx*sx + sy*sy + sz*sz + tx*tx + ty*ty + tz*tz);

    g_SA[pos]   = make_float4(sx, sy, sz, tx);
    g_SB[pos]   = make_float4(ty, tz, a, si);
    g_sidx[pos] = i;

    if (threadIdx.x == 0) g_cnt1[bx] = 0;            // ready for next replay
}

// ---------------- K2: triangular penalty + (last block) finalize ----------------
__global__ __launch_bounds__(TILE) void nms_fin_kernel(float* __restrict__ out,
                                                       int n) {
    const int bi = blockIdx.x;                       // row block
    const int g  = blockIdx.y;                       // tile group
    const int i  = bi * TILE + threadIdx.x;

    __shared__ __align__(16) float s_x[TILE], s_y[TILE], s_z[TILE];
    __shared__ __align__(16) float s_u[TILE], s_v[TILE], s_w[TILE];
    __shared__ __align__(16) float s_a[TILE], s_s[TILE];

    if (g * G > bi) {                                // no suppressor tiles here
        g_partial[i][g] = 0.0f;
    } else {
        const float4 Ai = g_SA[i];
        const float4 Bi = g_SB[i];
        const float twoL = 288.5390081777927f;       // 2*log2(e)/DELTA^2
        const ull w0 = pack2(twoL*Ai.x, twoL*Ai.x);
        const ull w1 = pack2(twoL*Ai.y, twoL*Ai.y);
        const ull w2 = pack2(twoL*Ai.z, twoL*Ai.z);
        const ull w3 = pack2(twoL*Ai.w, twoL*Ai.w);
        const ull w4 = pack2(twoL*Bi.x, twoL*Bi.x);
        const ull w5 = pack2(twoL*Bi.y, twoL*Bi.y);
        const ull ai2 = pack2(Bi.z, Bi.z);
        const float si = Bi.w;
        const float T = -30.0f;

        float pen = 0.0f;
        const int t1 = min(bi, g * G + (G - 1));

        for (int tj = g * G; tj <= t1; ++tj) {
            int j = tj * TILE + threadIdx.x;
            float4 A = g_SA[j];
            float4 B = g_SB[j];
            s_x[threadIdx.x] = A.x;
            s_y[threadIdx.x] = A.y;
            s_z[threadIdx.x] = A.z;
            s_u[threadIdx.x] = A.w;
            s_v[threadIdx.x] = B.x;
            s_w[threadIdx.x] = B.y;
            s_a[threadIdx.x] = B.z;
            s_s[threadIdx.x] = B.w;
            __syncthreads();

            const ulonglong2* px = (const ulonglong2*)s_x;
            const ulonglong2* py = (const ulonglong2*)s_y;
            const ulonglong2* pz = (const ulonglong2*)s_z;
            const ulonglong2* pu = (const ulonglong2*)s_u;
            const ulonglong2* pv = (const ulonglong2*)s_v;
            const ulonglong2* pw = (const ulonglong2*)s_w;
            const ulonglong2* pa = (const ulonglong2*)s_a;

            #pragma unroll 4
            for (int q = 0; q < TILE / 4; ++q) {
                ulonglong2 X = px[q];                // broadcast LDS.128
                ulonglong2 Y = py[q];
                ulonglong2 Z = pz[q];
                ulonglong2 U = pu[q];
                ulonglong2 V = pv[q];
                ulonglong2 W = pw[q];
                ulonglong2 AA = pa[q];

                ull acc0 = add2(ai2, AA.x);          // j = 4q, 4q+1
                ull acc1 = add2(ai2, AA.y);          // j = 4q+2, 4q+3
                acc0 = ffma2(w0, X.x, acc0);  acc1 = ffma2(w0, X.y, acc1);
                acc0 = ffma2(w1, Y.x, acc0);  acc1 = ffma2(w1, Y.y, acc1);
                acc0 = ffma2(w2, Z.x, acc0);  acc1 = ffma2(w2, Z.y, acc1);
                acc0 = ffma2(w3, U.x, acc0);  acc1 = ffma2(w3, U.y, acc1);
                acc0 = ffma2(w4, V.x, acc0);  acc1 = ffma2(w4, V.y, acc1);
                acc0 = ffma2(w5, W.x, acc0);  acc1 = ffma2(w5, W.y, acc1);

                float a0 = lo32(acc0), a1 = hi32(acc0);
                float a2 = lo32(acc1), a3 = hi32(acc1);

                // Rare path: strict score check handles ties and the
                // diagonal j==i (arg2 ~ 0, s_i > s_i false).
                if ((a0 > T) | (a1 > T) | (a2 > T) | (a3 > T)) {
                    int jb = q * 4;
                    if (a0 > T && s_s[jb+0] > si) pen += ex2f(a0);
                    if (a1 > T && s_s[jb+1] > si) pen += ex2f(a1);
                    if (a2 > T && s_s[jb+2] > si) pen += ex2f(a2);
                    if (a3 > T && s_s[jb+3] > si) pen += ex2f(a3);
                }
            }
            __syncthreads();
        }
        g_partial[i][g] = pen;
    }

    __threadfence();
    __shared__ int s_last;
    if (threadIdx.x == 0)
        s_last = (atomicAdd(&g_cnt2[bi], 1) == NGROUP - 1);
    __syncthreads();
    if (!s_last) return;

    // Last-arriving group block for this row block: finalize its 128 rows.
    const float4* pp = (const float4*)g_partial[i];  // 64B contiguous
    float4 a = pp[0], b = pp[1], c = pp[2], d = pp[3];
    float P = ((a.x + a.y) + (a.z + a.w)) + ((b.x + b.y) + (b.z + b.w))
            + ((c.x + c.y) + (c.z + c.w)) + ((d.x + d.y) + (d.z + d.w));
    const float C = 28.853900817779268f;             // log2(e)/SIGMA
    out[g_sidx[i]] = g_SB[i].w * ex2f(-P * C);

    g_tiecnt[i] = 0;                                 // reset for next replay
    if (threadIdx.x == 0) g_cnt2[bi] = 0;
}

extern "C" void kernel_launch(void* const* d_in, const int* in_sizes, int n_in,
                              void* d_out, int out_size) {
    const float* src = (const float*)d_in[0];
    const float* tgt = (const float*)d_in[1];
    const float* sc  = (const float*)d_in[2];
    float* out = (float*)d_out;
    const int n = in_sizes[2];                       // 8192

    dim3 g1(NBLK, RCH);
    rank_scatter_kernel<<<g1, TILE>>>(src, tgt, sc, n);
    dim3 g2(NBLK, NGROUP);
    nms_fin_kernel<<<g2, TILE>>>(out, n);
}